// round 8
// baseline (speedup 1.0000x reference)
#include <cuda_runtime.h>
#include <cuda_fp16.h>
#include <cstdint>

// ============================================================================
// IntraSentenceAttention, flash-style, fp16 mma.sync m16n8k16 + ldmatrix.
// Self-contained warps: each warp owns a 16-row band and the FULL j/d width,
// so P never leaves registers between phase A and phase B (no pair barriers,
// no P SMEM).
//   S = Xi·Xjᵀ   (A=Xi ldmatrix, B=Xj ldmatrix non-trans; k = d)
//   P = exp(S + min(i-j,10) + logmask)   (fp32 epilogue -> packed fp16 regs)
//   O += P·Xj    (A=P registers, B=Xj ldmatrix TRANS; k = j)
// B=32, T=1024, D=128. CTA 128 i-rows, 16 j-tiles of 64, 256 thr / 8 warps,
// 2 CTAs/SM.
// ============================================================================

namespace {
constexpr int Bb = 32, Tt = 1024, Dd = 128;
constexpr int TM = 128, TN = 64;
constexpr int NJT = Tt / TN;             // 16
constexpr float EPSF = 1e-7f;
constexpr float NEG_INF = -1e30f;

constexpr int PX = 272;                  // Xi/Xj row pitch bytes (128 fp16 + pad), ≡16 mod 128

// SMEM byte offsets
constexpr int SM_XI  = 0;                        // 128*272 = 34816
constexpr int SM_XJ0 = 34816;                    // 64*272  = 17408
constexpr int SM_XJ1 = 52224;                    // 17408
constexpr int SM_MI  = 69632;                    // 128 f
constexpr int SM_MJ0 = 70144;                    // 64 f (log-mask)
constexpr int SM_MJ1 = 70400;                    // 64 f
constexpr int SM_RP  = 70656;                    // 128 f
constexpr int SM_INV = 71168;                    // 128 f
constexpr int SMEM_BYTES = 71680;
}

__device__ uint2 g_x16[Bb * Tt * Dd / 4];   // x as fp16, [b][t][d] row-major
__device__ int   g_flags[2];                // zero-init; atomicOr of input-derived bits
                                            // => idempotent across calls/replays

// fp16 convert over all of x; blocks 0..63 additionally scan the mask words.
__global__ void cvt16_detect_kernel(const float4* __restrict__ x,
                                    const unsigned int* __restrict__ mw) {
    int i = blockIdx.x * 256 + threadIdx.x;
    float4 v = x[i];
    __half2 h0 = __floats2half2_rn(v.x, v.y);
    __half2 h1 = __floats2half2_rn(v.z, v.w);
    g_x16[i] = make_uint2(*(const uint32_t*)&h0, *(const uint32_t*)&h1);

    if (blockIdx.x < 64) {
        int wi = blockIdx.x * 256 + threadIdx.x;
        int not_int = 0, not_flt = 0;
        if (wi < (Bb * Tt) / 4) {
            unsigned wv = mw[wi];
            if (wv > 1u) not_int = 1;
            if (wv != 0u && wv != 0x3F800000u) not_flt = 1;
        }
        if (__ballot_sync(0xffffffffu, not_int) && (threadIdx.x & 31) == 0)
            atomicOr(&g_flags[0], 1);
        if (__ballot_sync(0xffffffffu, not_flt) && (threadIdx.x & 31) == 0)
            atomicOr(&g_flags[1], 1);
    }
}

__device__ __forceinline__ float get_mask(const void* m, int idx, int mode) {
    if (mode == 1) return ((const int*)m)[idx] ? 1.0f : 0.0f;
    if (mode == 2) return ((const float*)m)[idx];
    return ((const unsigned char*)m)[idx] ? 1.0f : 0.0f;
}

__device__ __forceinline__ uint32_t smem_u32(const void* p) {
    uint32_t a;
    asm("{ .reg .u64 t; cvta.to.shared.u64 t, %1; cvt.u32.u64 %0, t; }" : "=r"(a) : "l"(p));
    return a;
}
__device__ __forceinline__ void cp16(uint32_t dst, const void* src) {
    asm volatile("cp.async.cg.shared.global [%0], [%1], 16;" :: "r"(dst), "l"(src));
}
#define CP_COMMIT() asm volatile("cp.async.commit_group;" ::: "memory")
#define CP_WAIT0()  asm volatile("cp.async.wait_group 0;" ::: "memory")

__device__ __forceinline__ void ldsm4(uint32_t r[4], uint32_t a) {
    asm volatile("ldmatrix.sync.aligned.m8n8.x4.shared.b16 {%0,%1,%2,%3}, [%4];"
                 : "=r"(r[0]), "=r"(r[1]), "=r"(r[2]), "=r"(r[3]) : "r"(a));
}
__device__ __forceinline__ void ldsm4t(uint32_t r[4], uint32_t a) {
    asm volatile("ldmatrix.sync.aligned.m8n8.x4.trans.shared.b16 {%0,%1,%2,%3}, [%4];"
                 : "=r"(r[0]), "=r"(r[1]), "=r"(r[2]), "=r"(r[3]) : "r"(a));
}
__device__ __forceinline__ void mma_f16(float d[4], uint32_t a0, uint32_t a1,
                                        uint32_t a2, uint32_t a3,
                                        uint32_t b0, uint32_t b1) {
    asm volatile(
        "mma.sync.aligned.m16n8k16.row.col.f32.f16.f16.f32 "
        "{%0,%1,%2,%3}, {%4,%5,%6,%7}, {%8,%9}, {%0,%1,%2,%3};"
        : "+f"(d[0]), "+f"(d[1]), "+f"(d[2]), "+f"(d[3])
        : "r"(a0), "r"(a1), "r"(a2), "r"(a3), "r"(b0), "r"(b1));
}

// ---------------------------------------------------------------- main kernel
__global__ __launch_bounds__(256, 2)
void attn_mma(const void* __restrict__ mask, float* __restrict__ out) {
    extern __shared__ char sm[];
    const uint32_t sb = smem_u32(sm);

    const int tid  = threadIdx.x;
    const int w    = tid >> 5, lane = tid & 31;
    const int qrow = lane >> 2;       // 0..7
    const int qk   = lane & 3;        // 0..3
    const int arow0 = w * 16;         // this warp's 16-row band

    const int b  = blockIdx.y;
    const int i0 = blockIdx.x * TM;
    const int mode = (!g_flags[0]) ? 1 : ((!g_flags[1]) ? 2 : 0);
    const char* gx = (const char*)g_x16;     // fp16 x, 256B per row

    // ldmatrix lane-address offsets (bytes; per-ks/nb terms added at use)
    const int l7 = lane & 7, l8 = (lane >> 3) & 1, l16 = (lane >> 4) & 1;
    const uint32_t offA_xi = (uint32_t)((arow0 + l7 + 8 * l8) * PX + l16 * 16);
    const uint32_t offB_A  = (uint32_t)((l7 + 8 * l16) * PX + l8 * 16);
    const uint32_t offB_B  = (uint32_t)((l7 + 8 * l8) * PX + (8 * l16) * 2);

    // ---- stage Xi (cp.async) + tile-0 Xj + masks (log-mask: 0 / -inf) ----
    {
        const int xr = tid >> 1;                          // 0..127
        const size_t srow = (size_t)(b * Tt + i0 + xr) * 256;
        #pragma unroll
        for (int i = 0; i < 8; i++) {
            const int ch = (tid & 1) + 2 * i;
            cp16(sb + SM_XI + xr * PX + ch * 16, gx + srow + ch * 16);
        }
        const int jr = tid >> 2;                          // 0..63
        const size_t jrow = (size_t)(b * Tt + jr) * 256;
        #pragma unroll
        for (int i = 0; i < 4; i++) {
            const int ch = (tid & 3) + 4 * i;
            cp16(sb + SM_XJ0 + jr * PX + ch * 16, gx + jrow + ch * 16);
        }
        CP_COMMIT();
    }
    if (tid < TM) ((float*)(sm + SM_MI))[tid] = get_mask(mask, b * Tt + i0 + tid, mode);
    if (tid < TN)
        ((float*)(sm + SM_MJ0))[tid] =
            (get_mask(mask, b * Tt + tid, mode) != 0.0f) ? 0.0f : NEG_INF;

    float acc[16][4];                 // O: 16 rows x 128 cols per warp
    #pragma unroll
    for (int nf = 0; nf < 16; nf++)
        #pragma unroll
        for (int c = 0; c < 4; c++) acc[nf][c] = 0.0f;
    float rsum[2] = {0.f, 0.f};       // rows qrow, qrow+8

    for (int jt = 0; jt < NJT; ++jt) {
        const int j0 = jt * TN;
        const uint32_t xjb = sb + ((jt & 1) ? SM_XJ1 : SM_XJ0);
        const float* sMj = (const float*)(sm + ((jt & 1) ? SM_MJ1 : SM_MJ0));

        CP_WAIT0();
        __syncthreads();   // tile jt visible; all reads of the other buffer done

        // ---- issue cp.async for tile jt+1 into the other buffer ----
        if (jt + 1 < NJT) {
            const uint32_t dst = sb + (((jt + 1) & 1) ? SM_XJ1 : SM_XJ0);
            const int jr = tid >> 2;
            const size_t jrow = (size_t)(b * Tt + j0 + TN + jr) * 256;
            #pragma unroll
            for (int i = 0; i < 4; i++) {
                const int ch = (tid & 3) + 4 * i;
                cp16(dst + jr * PX + ch * 16, gx + jrow + ch * 16);
            }
            CP_COMMIT();
            if (tid < TN)
                ((float*)(sm + (((jt + 1) & 1) ? SM_MJ1 : SM_MJ0)))[tid] =
                    (get_mask(mask, b * Tt + j0 + TN + tid, mode) != 0.0f) ? 0.0f : NEG_INF;
        }

        // ============ phase A: S(16 x 64 per warp) = Xi · Xjᵀ ============
        float s[8][4];
        #pragma unroll
        for (int nf = 0; nf < 8; nf++)
            #pragma unroll
            for (int c = 0; c < 4; c++) s[nf][c] = 0.0f;

        #pragma unroll
        for (int ks = 0; ks < Dd / 16; ++ks) {
            uint32_t a[4];
            ldsm4(a, sb + SM_XI + offA_xi + ks * 32);
            #pragma unroll
            for (int nb = 0; nb < 4; nb++) {
                uint32_t bb[4];
                ldsm4(bb, xjb + offB_A + nb * 16 * PX + ks * 32);
                mma_f16(s[2 * nb],     a[0], a[1], a[2], a[3], bb[0], bb[1]);
                mma_f16(s[2 * nb + 1], a[0], a[1], a[2], a[3], bb[2], bb[3]);
            }
        }

        // ---- epilogue: P = exp(S + dist + logmask) -> packed fp16 registers ----
        uint32_t pk01[8], pk23[8];    // rows qrow / qrow+8, frag nf
        {
            const int rl0 = arow0 + qrow;
            const int ig0 = i0 + rl0;
            #pragma unroll
            for (int nf = 0; nf < 8; nf++) {
                const int jl = nf * 8 + 2 * qk;
                const int jg = j0 + jl;
                const float lm0 = sMj[jl], lm1 = sMj[jl + 1];
                float p0 = __expf(s[nf][0] + fminf((float)(ig0 - jg), 10.f) + lm0);
                float p1 = __expf(s[nf][1] + fminf((float)(ig0 - jg - 1), 10.f) + lm1);
                float p2 = __expf(s[nf][2] + fminf((float)(ig0 + 8 - jg), 10.f) + lm0);
                float p3 = __expf(s[nf][3] + fminf((float)(ig0 + 8 - jg - 1), 10.f) + lm1);
                rsum[0] += p0 + p1;
                rsum[1] += p2 + p3;
                __half2 h01 = __floats2half2_rn(p0, p1);
                __half2 h23 = __floats2half2_rn(p2, p3);
                pk01[nf] = *(const uint32_t*)&h01;
                pk23[nf] = *(const uint32_t*)&h23;
            }
        }

        // ============ phase B: O(16 x 128 per warp) += P · Xj ============
        // A-fragments come straight from pk registers: for k-chunk ks,
        // a = { pk01[2ks], pk23[2ks], pk01[2ks+1], pk23[2ks+1] }.
        #pragma unroll
        for (int ks = 0; ks < TN / 16; ++ks) {
            const uint32_t a0 = pk01[2 * ks], a1 = pk23[2 * ks];
            const uint32_t a2 = pk01[2 * ks + 1], a3 = pk23[2 * ks + 1];
            #pragma unroll
            for (int nb = 0; nb < 8; nb++) {
                uint32_t bb[4];
                ldsm4t(bb, xjb + offB_B + nb * 32 + ks * 16 * PX);
                mma_f16(acc[2 * nb],     a0, a1, a2, a3, bb[0], bb[1]);
                mma_f16(acc[2 * nb + 1], a0, a1, a2, a3, bb[2], bb[3]);
            }
        }
        // no end-of-loop barrier: the top barrier of jt+1 (after CP_WAIT0)
        // orders these reads before the cp.async that overwrites this buffer.
    }

    // ---- row-sum reduction + inverse (each row owned by exactly one warp) ----
    float* sRP  = (float*)(sm + SM_RP);
    float* sInv = (float*)(sm + SM_INV);
    #pragma unroll
    for (int rh = 0; rh < 2; rh++) {
        float v = rsum[rh];
        v += __shfl_xor_sync(0xffffffffu, v, 1);
        v += __shfl_xor_sync(0xffffffffu, v, 2);
        if (qk == 0) sRP[arow0 + rh * 8 + qrow] = v;
    }
    __syncthreads();
    if (tid < TM)
        sInv[tid] = ((float*)(sm + SM_MI))[tid] / (sRP[tid] + EPSF);
    __syncthreads();

    // ---- write O ----
    {
        const int rl0 = arow0 + qrow;
        const float inv0 = sInv[rl0], inv1 = sInv[rl0 + 8];
        float* o0 = out + ((size_t)b * Tt + i0 + rl0) * Dd;
        float* o1 = o0 + 8 * Dd;
        #pragma unroll
        for (int nf = 0; nf < 16; nf++) {
            const int cl = nf * 8 + 2 * qk;
            *(float2*)(o0 + cl) = make_float2(acc[nf][0] * inv0, acc[nf][1] * inv0);
            *(float2*)(o1 + cl) = make_float2(acc[nf][2] * inv1, acc[nf][3] * inv1);
        }
    }
}

extern "C" void kernel_launch(void* const* d_in, const int* in_sizes, int n_in,
                              void* d_out, int out_size) {
    const float* x   = (const float*)d_in[0];
    const void* mask = d_in[1];
    float* out       = (float*)d_out;

    cudaFuncSetAttribute(attn_mma, cudaFuncAttributeMaxDynamicSharedMemorySize, SMEM_BYTES);

    cvt16_detect_kernel<<<(Bb * Tt * Dd / 4) / 256, 256>>>(
        (const float4*)x, (const unsigned int*)mask);
    dim3 grid(Tt / TM, Bb);
    attn_mma<<<grid, 256, SMEM_BYTES>>>(mask, out);
}

// round 9
// speedup vs baseline: 1.0300x; 1.0300x over previous
#include <cuda_runtime.h>
#include <cuda_fp16.h>
#include <cstdint>

// ============================================================================
// IntraSentenceAttention, flash-style, fp16 mma.sync m16n8k16 + ldmatrix,
// with one-tile software pipelining: phase B of tile jt-1 is interleaved with
// phase A of tile jt (independent streams in one basic block), so tensor,
// LDSM and MUFU pipes overlap instead of running back-to-back.
//   S = Xi·Xjᵀ   (A=Xi ldmatrix, B=Xj ldmatrix non-trans; k = d)
//   P = exp(S + min(i-j,10) + logmask)   (fp32 epilogue -> packed fp16 regs)
//   O += P·Xj    (A=P registers, B=Xj ldmatrix TRANS; k = j)
// B=32, T=1024, D=128. CTA 128 i-rows, 16 j-tiles of 64, 256 thr / 8 warps,
// 2 CTAs/SM. Xj is TRIPLE buffered (reader jt-1, reader jt, writer jt+1).
// ============================================================================

namespace {
constexpr int Bb = 32, Tt = 1024, Dd = 128;
constexpr int TM = 128, TN = 64;
constexpr int NJT = Tt / TN;             // 16
constexpr float EPSF = 1e-7f;
constexpr float NEG_INF = -1e30f;

constexpr int PX = 272;                  // Xi/Xj row pitch bytes (128 fp16 + pad), ≡16 mod 128
constexpr int XJSZ = TN * PX;            // 17408

// SMEM byte offsets
constexpr int SM_XI  = 0;                        // 128*272 = 34816
constexpr int SM_XJ  = 34816;                    // 3 x 17408 = 52224
constexpr int SM_MI  = 87040;                    // 128 f
constexpr int SM_MJ  = 87552;                    // 3 x 64 f (256B stride)
constexpr int SM_RP  = 88320;                    // 128 f
constexpr int SM_INV = 88832;                    // 128 f
constexpr int SMEM_BYTES = 89344;
}

__device__ uint2 g_x16[Bb * Tt * Dd / 4];   // x as fp16, [b][t][d] row-major
__device__ int   g_flags[2];                // zero-init; atomicOr of input-derived bits
                                            // => idempotent across calls/replays

// fp16 convert over all of x; blocks 0..63 additionally scan the mask words.
__global__ void cvt16_detect_kernel(const float4* __restrict__ x,
                                    const unsigned int* __restrict__ mw) {
    int i = blockIdx.x * 256 + threadIdx.x;
    float4 v = x[i];
    __half2 h0 = __floats2half2_rn(v.x, v.y);
    __half2 h1 = __floats2half2_rn(v.z, v.w);
    g_x16[i] = make_uint2(*(const uint32_t*)&h0, *(const uint32_t*)&h1);

    if (blockIdx.x < 64) {
        int wi = blockIdx.x * 256 + threadIdx.x;
        int not_int = 0, not_flt = 0;
        if (wi < (Bb * Tt) / 4) {
            unsigned wv = mw[wi];
            if (wv > 1u) not_int = 1;
            if (wv != 0u && wv != 0x3F800000u) not_flt = 1;
        }
        if (__ballot_sync(0xffffffffu, not_int) && (threadIdx.x & 31) == 0)
            atomicOr(&g_flags[0], 1);
        if (__ballot_sync(0xffffffffu, not_flt) && (threadIdx.x & 31) == 0)
            atomicOr(&g_flags[1], 1);
    }
}

__device__ __forceinline__ float get_mask(const void* m, int idx, int mode) {
    if (mode == 1) return ((const int*)m)[idx] ? 1.0f : 0.0f;
    if (mode == 2) return ((const float*)m)[idx];
    return ((const unsigned char*)m)[idx] ? 1.0f : 0.0f;
}

__device__ __forceinline__ uint32_t smem_u32(const void* p) {
    uint32_t a;
    asm("{ .reg .u64 t; cvta.to.shared.u64 t, %1; cvt.u32.u64 %0, t; }" : "=r"(a) : "l"(p));
    return a;
}
__device__ __forceinline__ void cp16(uint32_t dst, const void* src) {
    asm volatile("cp.async.cg.shared.global [%0], [%1], 16;" :: "r"(dst), "l"(src));
}
#define CP_COMMIT() asm volatile("cp.async.commit_group;" ::: "memory")
#define CP_WAIT0()  asm volatile("cp.async.wait_group 0;" ::: "memory")

__device__ __forceinline__ void ldsm4(uint32_t r[4], uint32_t a) {
    asm volatile("ldmatrix.sync.aligned.m8n8.x4.shared.b16 {%0,%1,%2,%3}, [%4];"
                 : "=r"(r[0]), "=r"(r[1]), "=r"(r[2]), "=r"(r[3]) : "r"(a));
}
__device__ __forceinline__ void ldsm4t(uint32_t r[4], uint32_t a) {
    asm volatile("ldmatrix.sync.aligned.m8n8.x4.trans.shared.b16 {%0,%1,%2,%3}, [%4];"
                 : "=r"(r[0]), "=r"(r[1]), "=r"(r[2]), "=r"(r[3]) : "r"(a));
}
__device__ __forceinline__ void mma_f16(float d[4], uint32_t a0, uint32_t a1,
                                        uint32_t a2, uint32_t a3,
                                        uint32_t b0, uint32_t b1) {
    asm volatile(
        "mma.sync.aligned.m16n8k16.row.col.f32.f16.f16.f32 "
        "{%0,%1,%2,%3}, {%4,%5,%6,%7}, {%8,%9}, {%0,%1,%2,%3};"
        : "+f"(d[0]), "+f"(d[1]), "+f"(d[2]), "+f"(d[3])
        : "r"(a0), "r"(a1), "r"(a2), "r"(a3), "r"(b0), "r"(b1));
}

// ---------------------------------------------------------------- main kernel
__global__ __launch_bounds__(256, 2)
void attn_mma(const void* __restrict__ mask, float* __restrict__ out) {
    extern __shared__ char sm[];
    const uint32_t sb = smem_u32(sm);

    const int tid  = threadIdx.x;
    const int w    = tid >> 5, lane = tid & 31;
    const int qrow = lane >> 2;       // 0..7
    const int qk   = lane & 3;        // 0..3
    const int arow0 = w * 16;         // this warp's 16-row band

    const int b  = blockIdx.y;
    const int i0 = blockIdx.x * TM;
    const int mode = (!g_flags[0]) ? 1 : ((!g_flags[1]) ? 2 : 0);
    const char* gx = (const char*)g_x16;     // fp16 x, 256B per row

    // ldmatrix lane-address offsets (bytes; per-ks/nb terms added at use)
    const int l7 = lane & 7, l8 = (lane >> 3) & 1, l16 = (lane >> 4) & 1;
    const uint32_t offA_xi = (uint32_t)((arow0 + l7 + 8 * l8) * PX + l16 * 16);
    const uint32_t offB_A  = (uint32_t)((l7 + 8 * l16) * PX + l8 * 16);
    const uint32_t offB_B  = (uint32_t)((l7 + 8 * l8) * PX + (8 * l16) * 2);

    // ---- stage Xi (cp.async) + tile-0 Xj + masks (log-mask: 0 / -inf) ----
    {
        const int xr = tid >> 1;                          // 0..127
        const size_t srow = (size_t)(b * Tt + i0 + xr) * 256;
        #pragma unroll
        for (int i = 0; i < 8; i++) {
            const int ch = (tid & 1) + 2 * i;
            cp16(sb + SM_XI + xr * PX + ch * 16, gx + srow + ch * 16);
        }
        const int jr = tid >> 2;                          // 0..63
        const size_t jrow = (size_t)(b * Tt + jr) * 256;
        #pragma unroll
        for (int i = 0; i < 4; i++) {
            const int ch = (tid & 3) + 4 * i;
            cp16(sb + SM_XJ + jr * PX + ch * 16, gx + jrow + ch * 16);
        }
        CP_COMMIT();
    }
    if (tid < TM) ((float*)(sm + SM_MI))[tid] = get_mask(mask, b * Tt + i0 + tid, mode);
    if (tid < TN)
        ((float*)(sm + SM_MJ))[tid] =
            (get_mask(mask, b * Tt + tid, mode) != 0.0f) ? 0.0f : NEG_INF;

    float acc[16][4];                 // O: 16 rows x 128 cols per warp
    #pragma unroll
    for (int nf = 0; nf < 16; nf++)
        #pragma unroll
        for (int c = 0; c < 4; c++) acc[nf][c] = 0.0f;
    float rsum[2] = {0.f, 0.f};       // rows qrow, qrow+8

    uint32_t pkp01[8], pkp23[8];      // P of the PREVIOUS tile (phase-B A-operand)

    // prefetch tile jt+1 into buffer (jt+1)%3
    auto prefetch = [&](int jt) {
        const uint32_t dst = sb + SM_XJ + ((jt + 1) % 3) * XJSZ;
        const int jr = tid >> 2;
        const size_t jrow = (size_t)(b * Tt + (jt + 1) * TN + jr) * 256;
        #pragma unroll
        for (int i = 0; i < 4; i++) {
            const int ch = (tid & 3) + 4 * i;
            cp16(dst + jr * PX + ch * 16, gx + jrow + ch * 16);
        }
        CP_COMMIT();
        if (tid < TN)
            ((float*)(sm + SM_MJ + ((jt + 1) % 3) * 256))[tid] =
                (get_mask(mask, b * Tt + (jt + 1) * TN + tid, mode) != 0.0f) ? 0.0f : NEG_INF;
    };

    // phase A (S = Xi.Xj^T) + epilogue -> packed fp16 P fragments + rsum
    auto phaseA_epi = [&](int jt, uint32_t pk01[8], uint32_t pk23[8]) {
        const uint32_t xjb = sb + SM_XJ + (jt % 3) * XJSZ;
        const float* sMj = (const float*)(sm + SM_MJ + (jt % 3) * 256);
        float s[8][4];
        #pragma unroll
        for (int nf = 0; nf < 8; nf++)
            #pragma unroll
            for (int c = 0; c < 4; c++) s[nf][c] = 0.0f;
        #pragma unroll
        for (int ks = 0; ks < Dd / 16; ++ks) {
            uint32_t a[4];
            ldsm4(a, sb + SM_XI + offA_xi + ks * 32);
            #pragma unroll
            for (int nb = 0; nb < 4; nb++) {
                uint32_t bb[4];
                ldsm4(bb, xjb + offB_A + nb * 16 * PX + ks * 32);
                mma_f16(s[2 * nb],     a[0], a[1], a[2], a[3], bb[0], bb[1]);
                mma_f16(s[2 * nb + 1], a[0], a[1], a[2], a[3], bb[2], bb[3]);
            }
        }
        const int rl0 = arow0 + qrow;
        const int ig0 = i0 + rl0;
        const int j0 = jt * TN;
        #pragma unroll
        for (int nf = 0; nf < 8; nf++) {
            const int jl = nf * 8 + 2 * qk;
            const int jg = j0 + jl;
            const float lm0 = sMj[jl], lm1 = sMj[jl + 1];
            float p0 = __expf(s[nf][0] + fminf((float)(ig0 - jg), 10.f) + lm0);
            float p1 = __expf(s[nf][1] + fminf((float)(ig0 - jg - 1), 10.f) + lm1);
            float p2 = __expf(s[nf][2] + fminf((float)(ig0 + 8 - jg), 10.f) + lm0);
            float p3 = __expf(s[nf][3] + fminf((float)(ig0 + 8 - jg - 1), 10.f) + lm1);
            rsum[0] += p0 + p1;
            rsum[1] += p2 + p3;
            __half2 h01 = __floats2half2_rn(p0, p1);
            __half2 h23 = __floats2half2_rn(p2, p3);
            pk01[nf] = *(const uint32_t*)&h01;
            pk23[nf] = *(const uint32_t*)&h23;
        }
    };

    // phase B: O += P(prev tile) . Xj(prev tile); A-operand from pk registers
    auto phaseB = [&](int jtprev) {
        const uint32_t xjb = sb + SM_XJ + (jtprev % 3) * XJSZ;
        #pragma unroll
        for (int ks = 0; ks < TN / 16; ++ks) {
            const uint32_t a0 = pkp01[2 * ks], a1 = pkp23[2 * ks];
            const uint32_t a2 = pkp01[2 * ks + 1], a3 = pkp23[2 * ks + 1];
            #pragma unroll
            for (int nb = 0; nb < 8; nb++) {
                uint32_t bb[4];
                ldsm4t(bb, xjb + offB_B + nb * 32 + ks * 16 * PX);
                mma_f16(acc[2 * nb],     a0, a1, a2, a3, bb[0], bb[1]);
                mma_f16(acc[2 * nb + 1], a0, a1, a2, a3, bb[2], bb[3]);
            }
        }
    };

    // ---- pipelined main loop: A(jt) and B(jt-1) interleave in one BB ----
    CP_WAIT0();
    __syncthreads();
    prefetch(0);
    phaseA_epi(0, pkp01, pkp23);

    for (int jt = 1; jt < NJT; ++jt) {
        CP_WAIT0();
        __syncthreads();   // buf jt ready; everyone done with buf (jt+1)%3 == (jt-2)%3
        if (jt + 1 < NJT) prefetch(jt);

        uint32_t pkn01[8], pkn23[8];
        phaseB(jt - 1);              // independent of phase A(jt): ptxas interleaves
        phaseA_epi(jt, pkn01, pkn23);

        #pragma unroll
        for (int nf = 0; nf < 8; nf++) { pkp01[nf] = pkn01[nf]; pkp23[nf] = pkn23[nf]; }
    }
    phaseB(NJT - 1);   // drain

    // ---- row-sum reduction + inverse (each row owned by exactly one warp) ----
    float* sRP  = (float*)(sm + SM_RP);
    float* sInv = (float*)(sm + SM_INV);
    #pragma unroll
    for (int rh = 0; rh < 2; rh++) {
        float v = rsum[rh];
        v += __shfl_xor_sync(0xffffffffu, v, 1);
        v += __shfl_xor_sync(0xffffffffu, v, 2);
        if (qk == 0) sRP[arow0 + rh * 8 + qrow] = v;
    }
    __syncthreads();
    if (tid < TM)
        sInv[tid] = ((float*)(sm + SM_MI))[tid] / (sRP[tid] + EPSF);
    __syncthreads();

    // ---- write O ----
    {
        const int rl0 = arow0 + qrow;
        const float inv0 = sInv[rl0], inv1 = sInv[rl0 + 8];
        float* o0 = out + ((size_t)b * Tt + i0 + rl0) * Dd;
        float* o1 = o0 + 8 * Dd;
        #pragma unroll
        for (int nf = 0; nf < 16; nf++) {
            const int cl = nf * 8 + 2 * qk;
            *(float2*)(o0 + cl) = make_float2(acc[nf][0] * inv0, acc[nf][1] * inv0);
            *(float2*)(o1 + cl) = make_float2(acc[nf][2] * inv1, acc[nf][3] * inv1);
        }
    }
}

extern "C" void kernel_launch(void* const* d_in, const int* in_sizes, int n_in,
                              void* d_out, int out_size) {
    const float* x   = (const float*)d_in[0];
    const void* mask = d_in[1];
    float* out       = (float*)d_out;

    cudaFuncSetAttribute(attn_mma, cudaFuncAttributeMaxDynamicSharedMemorySize, SMEM_BYTES);

    cvt16_detect_kernel<<<(Bb * Tt * Dd / 4) / 256, 256>>>(
        (const float4*)x, (const unsigned int*)mask);
    dim3 grid(Tt / TM, Bb);
    attn_mma<<<grid, 256, SMEM_BYTES>>>(mask, out);
}

// round 10
// speedup vs baseline: 1.0654x; 1.0344x over previous
#include <cuda_runtime.h>
#include <cuda_fp16.h>
#include <cstdint>

// ============================================================================
// IntraSentenceAttention, flash-style, fp16 mma.sync m16n8k16 + ldmatrix,
// one-tile software pipelining (phase B of jt-1 interleaves with phase A of jt).
//   S = Xi·Xjᵀ   (A=Xi ldmatrix, B=Xj ldmatrix non-trans; k = d)
//   P = exp(S + min(i-j,10) + logmask)   (fp32 epilogue -> packed fp16 regs)
//   O += P·Xj    (A=P registers, B=Xj ldmatrix TRANS; k = j)
// B=32, T=1024, D=128. CTA 128 i-rows, 16 j-tiles of 64, 256 thr / 8 warps,
// 2 CTAs/SM. Xj triple-buffered; the batch's full log-mask (1024 f) is loaded
// once into SMEM; distance term computed in pure fp32 (no per-element I2F).
// ============================================================================

namespace {
constexpr int Bb = 32, Tt = 1024, Dd = 128;
constexpr int TM = 128, TN = 64;
constexpr int NJT = Tt / TN;             // 16
constexpr float EPSF = 1e-7f;
constexpr float NEG_INF = -1e30f;

constexpr int PX = 272;                  // Xi/Xj row pitch bytes (128 fp16 + pad), ≡16 mod 128
constexpr int XJSZ = TN * PX;            // 17408

// SMEM byte offsets
constexpr int SM_XI  = 0;                        // 128*272 = 34816
constexpr int SM_XJ  = 34816;                    // 3 x 17408 = 52224
constexpr int SM_LM  = 87040;                    // 1024 f log-mask (4 KB)
constexpr int SM_RP  = 91136;                    // 128 f
constexpr int SM_INV = 91648;                    // 128 f
constexpr int SMEM_BYTES = 92160;                // 2 CTAs/SM: 184 KB <= 227 KB
}

__device__ uint2 g_x16[Bb * Tt * Dd / 4];   // x as fp16, [b][t][d] row-major
__device__ int   g_flags[2];                // zero-init; atomicOr of input-derived bits
                                            // => idempotent across calls/replays

// fp16 convert over all of x; blocks 0..63 additionally scan the mask words.
__global__ void cvt16_detect_kernel(const float4* __restrict__ x,
                                    const unsigned int* __restrict__ mw) {
    int i = blockIdx.x * 256 + threadIdx.x;
    float4 v = x[i];
    __half2 h0 = __floats2half2_rn(v.x, v.y);
    __half2 h1 = __floats2half2_rn(v.z, v.w);
    g_x16[i] = make_uint2(*(const uint32_t*)&h0, *(const uint32_t*)&h1);

    if (blockIdx.x < 64) {
        int wi = blockIdx.x * 256 + threadIdx.x;
        int not_int = 0, not_flt = 0;
        if (wi < (Bb * Tt) / 4) {
            unsigned wv = mw[wi];
            if (wv > 1u) not_int = 1;
            if (wv != 0u && wv != 0x3F800000u) not_flt = 1;
        }
        if (__ballot_sync(0xffffffffu, not_int) && (threadIdx.x & 31) == 0)
            atomicOr(&g_flags[0], 1);
        if (__ballot_sync(0xffffffffu, not_flt) && (threadIdx.x & 31) == 0)
            atomicOr(&g_flags[1], 1);
    }
}

__device__ __forceinline__ float get_mask(const void* m, int idx, int mode) {
    if (mode == 1) return ((const int*)m)[idx] ? 1.0f : 0.0f;
    if (mode == 2) return ((const float*)m)[idx];
    return ((const unsigned char*)m)[idx] ? 1.0f : 0.0f;
}

__device__ __forceinline__ uint32_t smem_u32(const void* p) {
    uint32_t a;
    asm("{ .reg .u64 t; cvta.to.shared.u64 t, %1; cvt.u32.u64 %0, t; }" : "=r"(a) : "l"(p));
    return a;
}
__device__ __forceinline__ void cp16(uint32_t dst, const void* src) {
    asm volatile("cp.async.cg.shared.global [%0], [%1], 16;" :: "r"(dst), "l"(src));
}
#define CP_COMMIT() asm volatile("cp.async.commit_group;" ::: "memory")
#define CP_WAIT0()  asm volatile("cp.async.wait_group 0;" ::: "memory")

__device__ __forceinline__ void ldsm4(uint32_t r[4], uint32_t a) {
    asm volatile("ldmatrix.sync.aligned.m8n8.x4.shared.b16 {%0,%1,%2,%3}, [%4];"
                 : "=r"(r[0]), "=r"(r[1]), "=r"(r[2]), "=r"(r[3]) : "r"(a));
}
__device__ __forceinline__ void ldsm4t(uint32_t r[4], uint32_t a) {
    asm volatile("ldmatrix.sync.aligned.m8n8.x4.trans.shared.b16 {%0,%1,%2,%3}, [%4];"
                 : "=r"(r[0]), "=r"(r[1]), "=r"(r[2]), "=r"(r[3]) : "r"(a));
}
__device__ __forceinline__ void mma_f16(float d[4], uint32_t a0, uint32_t a1,
                                        uint32_t a2, uint32_t a3,
                                        uint32_t b0, uint32_t b1) {
    asm volatile(
        "mma.sync.aligned.m16n8k16.row.col.f32.f16.f16.f32 "
        "{%0,%1,%2,%3}, {%4,%5,%6,%7}, {%8,%9}, {%0,%1,%2,%3};"
        : "+f"(d[0]), "+f"(d[1]), "+f"(d[2]), "+f"(d[3])
        : "r"(a0), "r"(a1), "r"(a2), "r"(a3), "r"(b0), "r"(b1));
}

// ---------------------------------------------------------------- main kernel
__global__ __launch_bounds__(256, 2)
void attn_mma(const void* __restrict__ mask, float* __restrict__ out) {
    extern __shared__ char sm[];
    const uint32_t sb = smem_u32(sm);

    const int tid  = threadIdx.x;
    const int w    = tid >> 5, lane = tid & 31;
    const int qrow = lane >> 2;       // 0..7
    const int qk   = lane & 3;        // 0..3
    const int arow0 = w * 16;         // this warp's 16-row band

    const int b  = blockIdx.y;
    const int i0 = blockIdx.x * TM;
    const int mode = (!g_flags[0]) ? 1 : ((!g_flags[1]) ? 2 : 0);
    const char* gx = (const char*)g_x16;     // fp16 x, 256B per row

    // ldmatrix lane-address offsets (bytes; per-ks/nb terms added at use)
    const int l7 = lane & 7, l8 = (lane >> 3) & 1, l16 = (lane >> 4) & 1;
    const uint32_t offA_xi = (uint32_t)((arow0 + l7 + 8 * l8) * PX + l16 * 16);
    const uint32_t offB_A  = (uint32_t)((l7 + 8 * l16) * PX + l8 * 16);
    const uint32_t offB_B  = (uint32_t)((l7 + 8 * l8) * PX + (8 * l16) * 2);

    float* sLM = (float*)(sm + SM_LM);

    // ---- stage Xi (cp.async) + tile-0 Xj + the batch's full log-mask ----
    {
        const int xr = tid >> 1;                          // 0..127
        const size_t srow = (size_t)(b * Tt + i0 + xr) * 256;
        #pragma unroll
        for (int i = 0; i < 8; i++) {
            const int ch = (tid & 1) + 2 * i;
            cp16(sb + SM_XI + xr * PX + ch * 16, gx + srow + ch * 16);
        }
        const int jr = tid >> 2;                          // 0..63
        const size_t jrow = (size_t)(b * Tt + jr) * 256;
        #pragma unroll
        for (int i = 0; i < 4; i++) {
            const int ch = (tid & 3) + 4 * i;
            cp16(sb + SM_XJ + jr * PX + ch * 16, gx + jrow + ch * 16);
        }
        CP_COMMIT();
    }
    #pragma unroll
    for (int e = 0; e < 4; e++) {
        const int t = tid + 256 * e;
        sLM[t] = (get_mask(mask, b * Tt + t, mode) != 0.0f) ? 0.0f : NEG_INF;
    }

    float acc[16][4];                 // O: 16 rows x 128 cols per warp
    #pragma unroll
    for (int nf = 0; nf < 16; nf++)
        #pragma unroll
        for (int c = 0; c < 4; c++) acc[nf][c] = 0.0f;
    float rsum[2] = {0.f, 0.f};       // rows qrow, qrow+8

    uint32_t pkp01[8], pkp23[8];      // P of the PREVIOUS tile (phase-B A-operand)
    const float qk2f = (float)(2 * qk);

    // prefetch tile jt+1 into buffer (jt+1)%3 (pure cp.async)
    auto prefetch = [&](int jt) {
        const uint32_t dst = sb + SM_XJ + ((jt + 1) % 3) * XJSZ;
        const int jr = tid >> 2;
        const size_t jrow = (size_t)(b * Tt + (jt + 1) * TN + jr) * 256;
        #pragma unroll
        for (int i = 0; i < 4; i++) {
            const int ch = (tid & 3) + 4 * i;
            cp16(dst + jr * PX + ch * 16, gx + jrow + ch * 16);
        }
        CP_COMMIT();
    };

    // phase A (S = Xi.Xj^T) + epilogue -> packed fp16 P fragments + rsum
    auto phaseA_epi = [&](int jt, uint32_t pk01[8], uint32_t pk23[8]) {
        const uint32_t xjb = sb + SM_XJ + (jt % 3) * XJSZ;
        float s[8][4];
        #pragma unroll
        for (int nf = 0; nf < 8; nf++)
            #pragma unroll
            for (int c = 0; c < 4; c++) s[nf][c] = 0.0f;
        #pragma unroll
        for (int ks = 0; ks < Dd / 16; ++ks) {
            uint32_t a[4];
            ldsm4(a, sb + SM_XI + offA_xi + ks * 32);
            #pragma unroll
            for (int nb = 0; nb < 4; nb++) {
                uint32_t bb[4];
                ldsm4(bb, xjb + offB_A + nb * 16 * PX + ks * 32);
                mma_f16(s[2 * nb],     a[0], a[1], a[2], a[3], bb[0], bb[1]);
                mma_f16(s[2 * nb + 1], a[0], a[1], a[2], a[3], bb[2], bb[3]);
            }
        }
        const int j0 = jt * TN;
        // fq = (i_glob - j0) - 2qk as float; per-nf distance = fq - 8nf (+consts)
        const float fq = (float)(i0 + arow0 + qrow - j0) - qk2f;
        const float* lmj = sLM + j0;
        #pragma unroll
        for (int nf = 0; nf < 8; nf++) {
            const float2 lm = *(const float2*)(lmj + nf * 8 + 2 * qk);
            const float d0 = fq - (float)(nf * 8);
            float p0 = __expf(s[nf][0] + fminf(d0,        10.f) + lm.x);
            float p1 = __expf(s[nf][1] + fminf(d0 - 1.f,  10.f) + lm.y);
            float p2 = __expf(s[nf][2] + fminf(d0 + 8.f,  10.f) + lm.x);
            float p3 = __expf(s[nf][3] + fminf(d0 + 7.f,  10.f) + lm.y);
            rsum[0] += p0 + p1;
            rsum[1] += p2 + p3;
            __half2 h01 = __floats2half2_rn(p0, p1);
            __half2 h23 = __floats2half2_rn(p2, p3);
            pk01[nf] = *(const uint32_t*)&h01;
            pk23[nf] = *(const uint32_t*)&h23;
        }
    };

    // phase B: O += P(prev tile) . Xj(prev tile); A-operand from pk registers
    auto phaseB = [&](int jtprev) {
        const uint32_t xjb = sb + SM_XJ + (jtprev % 3) * XJSZ;
        #pragma unroll
        for (int ks = 0; ks < TN / 16; ++ks) {
            const uint32_t a0 = pkp01[2 * ks], a1 = pkp23[2 * ks];
            const uint32_t a2 = pkp01[2 * ks + 1], a3 = pkp23[2 * ks + 1];
            #pragma unroll
            for (int nb = 0; nb < 8; nb++) {
                uint32_t bb[4];
                ldsm4t(bb, xjb + offB_B + nb * 32 + ks * 16 * PX);
                mma_f16(acc[2 * nb],     a0, a1, a2, a3, bb[0], bb[1]);
                mma_f16(acc[2 * nb + 1], a0, a1, a2, a3, bb[2], bb[3]);
            }
        }
    };

    // ---- pipelined main loop: A(jt) and B(jt-1) interleave in one BB ----
    CP_WAIT0();
    __syncthreads();
    prefetch(0);
    phaseA_epi(0, pkp01, pkp23);

    for (int jt = 1; jt < NJT; ++jt) {
        CP_WAIT0();
        __syncthreads();   // buf jt ready; everyone done with buf (jt+1)%3 == (jt-2)%3
        if (jt + 1 < NJT) prefetch(jt);

        uint32_t pkn01[8], pkn23[8];
        phaseB(jt - 1);              // independent of phase A(jt): ptxas interleaves
        phaseA_epi(jt, pkn01, pkn23);

        #pragma unroll
        for (int nf = 0; nf < 8; nf++) { pkp01[nf] = pkn01[nf]; pkp23[nf] = pkn23[nf]; }
    }
    phaseB(NJT - 1);   // drain

    // ---- row-sum reduction + inverse (each row owned by exactly one warp) ----
    float* sRP  = (float*)(sm + SM_RP);
    float* sInv = (float*)(sm + SM_INV);
    #pragma unroll
    for (int rh = 0; rh < 2; rh++) {
        float v = rsum[rh];
        v += __shfl_xor_sync(0xffffffffu, v, 1);
        v += __shfl_xor_sync(0xffffffffu, v, 2);
        if (qk == 0) sRP[arow0 + rh * 8 + qrow] = v;
    }
    __syncthreads();
    if (tid < TM) {
        const float mi = (sLM[i0 - (i0 & ~(Tt - 1)) + tid + (i0 & (Tt - 1)) - (i0 & (Tt - 1))] == 0.0f) ? 1.0f : 0.0f;  // sLM[i0+tid], i0<Tt
        sInv[tid] = ((sLM[i0 + tid] == 0.0f) ? 1.0f : 0.0f) / (sRP[tid] + EPSF);
        (void)mi;
    }
    __syncthreads();

    // ---- write O ----
    {
        const int rl0 = arow0 + qrow;
        const float inv0 = sInv[rl0], inv1 = sInv[rl0 + 8];
        float* o0 = out + ((size_t)b * Tt + i0 + rl0) * Dd;
        float* o1 = o0 + 8 * Dd;
        #pragma unroll
        for (int nf = 0; nf < 16; nf++) {
            const int cl = nf * 8 + 2 * qk;
            *(float2*)(o0 + cl) = make_float2(acc[nf][0] * inv0, acc[nf][1] * inv0);
            *(float2*)(o1 + cl) = make_float2(acc[nf][2] * inv1, acc[nf][3] * inv1);
        }
    }
}

extern "C" void kernel_launch(void* const* d_in, const int* in_sizes, int n_in,
                              void* d_out, int out_size) {
    const float* x   = (const float*)d_in[0];
    const void* mask = d_in[1];
    float* out       = (float*)d_out;

    cudaFuncSetAttribute(attn_mma, cudaFuncAttributeMaxDynamicSharedMemorySize, SMEM_BYTES);

    cvt16_detect_kernel<<<(Bb * Tt * Dd / 4) / 256, 256>>>(
        (const float4*)x, (const unsigned int*)mask);
    dim3 grid(Tt / TM, Bb);
    attn_mma<<<grid, 256, SMEM_BYTES>>>(mask, out);
}